// round 1
// baseline (speedup 1.0000x reference)
#include <cuda_runtime.h>
#include <cstdint>
#include <cstddef>

// ---------------------------------------------------------------------------
// Problem constants
// ---------------------------------------------------------------------------
#define E_DIM   1024
#define H_DIM   16
#define D_DIM   64
#define B_DIM   2
#define T_DIM   32
#define N_DIM   256
#define MTOK    (B_DIM * T_DIM * N_DIM)   // 16384 tokens total
#define MTOK_B  (T_DIM * N_DIM)           // 8192 tokens per batch
#define KSEL    256
#define MAXLEN  512
#define RB_ONE  ((2 * MAXLEN - 1) * H_DIM) // stride per attention index in rel_bias
#define SPLITK  8
#define OUT_ROWS 448                      // 256 + 128 + 64

// ---------------------------------------------------------------------------
// Scratch (device globals — no allocations allowed)
// ---------------------------------------------------------------------------
__device__ float g_Q[MTOK * E_DIM];
__device__ float g_Kb[MTOK * E_DIM];
__device__ float g_Vb[MTOK * E_DIM];
__device__ float g_Cb[MTOK * E_DIM];
__device__ float g_Hb[MTOK * E_DIM];
__device__ float g_SC[MTOK * KSEL];
__device__ float g_SEL[B_DIM * KSEL * E_DIM];

// ---------------------------------------------------------------------------
// GEMM: C[M,N] = A[M,Kd] @ B[Kd,N] + bias[N]   (row-major, all dims %128/%16==0)
// 128x128 block tile, 16 k-slice, 8x8 per thread, 256 threads.
// ---------------------------------------------------------------------------
__global__ __launch_bounds__(256, 2)
void gemm_nn_bias(const float* __restrict__ A, const float* __restrict__ B,
                  const float* __restrict__ bias, float* __restrict__ C,
                  int M, int N, int Kd)
{
    __shared__ float As[16][128];
    __shared__ float Bs[16][128];

    const int tid = threadIdx.x;
    const int bx = blockIdx.x;   // N tile
    const int by = blockIdx.y;   // M tile

    const float* Ab = A + (size_t)by * 128 * Kd;
    const float* Bb = B + (size_t)bx * 128;

    const int arow = tid >> 2;          // 0..63
    const int acol = (tid & 3) << 2;    // 0,4,8,12
    const int brow = tid >> 5;          // 0..7
    const int bcol = (tid & 31) << 2;   // 0..124

    const int tx = tid & 15;
    const int ty = tid >> 4;

    float acc[8][8];
#pragma unroll
    for (int i = 0; i < 8; i++)
#pragma unroll
        for (int j = 0; j < 8; j++) acc[i][j] = 0.f;

    for (int k0 = 0; k0 < Kd; k0 += 16) {
        float4 a0 = *(const float4*)&Ab[(size_t)arow * Kd + k0 + acol];
        float4 a1 = *(const float4*)&Ab[(size_t)(arow + 64) * Kd + k0 + acol];
        As[acol + 0][arow] = a0.x; As[acol + 1][arow] = a0.y;
        As[acol + 2][arow] = a0.z; As[acol + 3][arow] = a0.w;
        As[acol + 0][arow + 64] = a1.x; As[acol + 1][arow + 64] = a1.y;
        As[acol + 2][arow + 64] = a1.z; As[acol + 3][arow + 64] = a1.w;

        *(float4*)&Bs[brow][bcol]     = *(const float4*)&Bb[(size_t)(k0 + brow) * N + bcol];
        *(float4*)&Bs[brow + 8][bcol] = *(const float4*)&Bb[(size_t)(k0 + brow + 8) * N + bcol];
        __syncthreads();

#pragma unroll
        for (int kk = 0; kk < 16; kk++) {
            float ar[8], br[8];
            *(float4*)&ar[0] = *(const float4*)&As[kk][ty * 8];
            *(float4*)&ar[4] = *(const float4*)&As[kk][ty * 8 + 4];
            *(float4*)&br[0] = *(const float4*)&Bs[kk][tx * 8];
            *(float4*)&br[4] = *(const float4*)&Bs[kk][tx * 8 + 4];
#pragma unroll
            for (int i = 0; i < 8; i++)
#pragma unroll
                for (int j = 0; j < 8; j++)
                    acc[i][j] += ar[i] * br[j];
        }
        __syncthreads();
    }

    const int colbase = bx * 128 + tx * 8;
    float bb[8];
#pragma unroll
    for (int j = 0; j < 8; j++) bb[j] = bias ? bias[colbase + j] : 0.f;

#pragma unroll
    for (int i = 0; i < 8; i++) {
        size_t row = (size_t)by * 128 + ty * 8 + i;
        float* cp = C + row * N + colbase;
        float4 v0, v1;
        v0.x = acc[i][0] + bb[0]; v0.y = acc[i][1] + bb[1];
        v0.z = acc[i][2] + bb[2]; v0.w = acc[i][3] + bb[3];
        v1.x = acc[i][4] + bb[4]; v1.y = acc[i][5] + bb[5];
        v1.z = acc[i][6] + bb[6]; v1.w = acc[i][7] + bb[7];
        *(float4*)&cp[0] = v0;
        *(float4*)&cp[4] = v1;
    }
}

// ---------------------------------------------------------------------------
// Split-K GEMM with A stored column-major relative to the output rows:
//   per batch b:  C[r, n] += sum_m Wts[b][m][r] * Flat[b][m][n]
// Wts: [B][MTOK_B][KSEL] (we read it "transposed" which is coalesced here),
// Flat: [B][MTOK_B][E], C: [B][KSEL][E] (pre-zeroed; atomic accumulate).
// grid: (E/128, KSEL/128, B*SPLITK)
// ---------------------------------------------------------------------------
__global__ __launch_bounds__(256, 2)
void gemm_sel_atomic(const float* __restrict__ Wts, const float* __restrict__ Flat,
                     float* __restrict__ Csel)
{
    __shared__ float As[16][128];
    __shared__ float Bs[16][128];

    const int tid = threadIdx.x;
    const int bx = blockIdx.x;                 // e tile
    const int by = blockIdx.y;                 // sel-row tile
    const int b  = blockIdx.z / SPLITK;
    const int sl = blockIdx.z % SPLITK;

    const float* A = Wts  + (size_t)b * MTOK_B * KSEL;
    const float* B = Flat + (size_t)b * MTOK_B * E_DIM;
    float*       C = Csel + (size_t)b * KSEL * E_DIM;

    const int lr = (tid & 31) << 2;   // 0..124
    const int lk = tid >> 5;          // 0..7
    const int tx = tid & 15;
    const int ty = tid >> 4;

    const int kbeg = sl * (MTOK_B / SPLITK);
    const int kend = kbeg + (MTOK_B / SPLITK);

    float acc[8][8];
#pragma unroll
    for (int i = 0; i < 8; i++)
#pragma unroll
        for (int j = 0; j < 8; j++) acc[i][j] = 0.f;

    for (int k0 = kbeg; k0 < kend; k0 += 16) {
        *(float4*)&As[lk][lr]     = *(const float4*)&A[(size_t)(k0 + lk) * KSEL + by * 128 + lr];
        *(float4*)&As[lk + 8][lr] = *(const float4*)&A[(size_t)(k0 + lk + 8) * KSEL + by * 128 + lr];
        *(float4*)&Bs[lk][lr]     = *(const float4*)&B[(size_t)(k0 + lk) * E_DIM + bx * 128 + lr];
        *(float4*)&Bs[lk + 8][lr] = *(const float4*)&B[(size_t)(k0 + lk + 8) * E_DIM + bx * 128 + lr];
        __syncthreads();

#pragma unroll
        for (int kk = 0; kk < 16; kk++) {
            float ar[8], br[8];
            *(float4*)&ar[0] = *(const float4*)&As[kk][ty * 8];
            *(float4*)&ar[4] = *(const float4*)&As[kk][ty * 8 + 4];
            *(float4*)&br[0] = *(const float4*)&Bs[kk][tx * 8];
            *(float4*)&br[4] = *(const float4*)&Bs[kk][tx * 8 + 4];
#pragma unroll
            for (int i = 0; i < 8; i++)
#pragma unroll
                for (int j = 0; j < 8; j++)
                    acc[i][j] += ar[i] * br[j];
        }
        __syncthreads();
    }

#pragma unroll
    for (int i = 0; i < 8; i++) {
        float* cp = C + (size_t)(by * 128 + ty * 8 + i) * E_DIM + bx * 128 + tx * 8;
#pragma unroll
        for (int j = 0; j < 8; j++)
            atomicAdd(&cp[j], acc[i][j]);
    }
}

// ---------------------------------------------------------------------------
// Fused relative-bias multihead attention (one block per (head, group)).
// Q/K/V/Ctx are [MTOK, E] in the global [B,T,N] token order.
// group -> base token: base_m = (g/div)*mulq + (g%div)*mulr; seq pos t is at
// token base_m + t*stepTok. Head picks E-slice [h*64, h*64+64).
// Templated on S (256 spatial, 32 temporal).  D fixed = 64.
// smem: Kt2[32][S+1] (float2 over d-pairs, t-contiguous), Vs2[S][32], rbh[2S-1]
// ---------------------------------------------------------------------------
template <int S>
__global__ __launch_bounds__(256)
void attn_kernel(const float* __restrict__ Q, const float* __restrict__ K,
                 const float* __restrict__ V, float* __restrict__ Ctx,
                 const float* __restrict__ rb,     // rel_bias for this attn idx
                 int div, int mulq, int mulr, int stepTok)
{
    const int h = blockIdx.x;
    const int g = blockIdx.y;
    const int base_m = (g / div) * mulq + (g % div) * mulr;
    const size_t baseE = (size_t)base_m * E_DIM + h * D_DIM;
    const size_t stepE = (size_t)stepTok * E_DIM;

    extern __shared__ float sm[];
    float2* Kt2 = (float2*)sm;               // [32][S+1]
    float2* Vs2 = Kt2 + 32 * (S + 1);        // [S][32]
    float*  rbh = (float*)(Vs2 + S * 32);    // [2S-1]

    const int tid = threadIdx.x;

    // cooperative load of K (d-pair transposed) and V
    for (int idx = tid; idx < S * 32; idx += 256) {
        int t = idx >> 5, d2 = idx & 31;
        size_t off = baseE + (size_t)t * stepE;
        Kt2[d2 * (S + 1) + t] = *(const float2*)&K[off + 2 * d2];
        Vs2[idx]              = *(const float2*)&V[off + 2 * d2];
    }
    for (int i = tid; i < 2 * S - 1; i += 256)
        rbh[i] = rb[(size_t)(MAXLEN - S + i) * H_DIM + h];
    __syncthreads();

    const int lane = tid & 31;
    const int warp = tid >> 5;
    const int NT = S / 32;

    for (int q = warp; q < S; q += 8) {
        size_t qoff = baseE + (size_t)q * stepE;
        float2 ql = *(const float2*)&Q[qoff + 2 * lane];

        float s[NT];
#pragma unroll
        for (int tb = 0; tb < NT; tb++) s[tb] = 0.f;

#pragma unroll 4
        for (int d2 = 0; d2 < 32; d2++) {
            float qx = __shfl_sync(0xffffffffu, ql.x, d2);
            float qy = __shfl_sync(0xffffffffu, ql.y, d2);
            const float2* kr = &Kt2[d2 * (S + 1) + lane];
#pragma unroll
            for (int tb = 0; tb < NT; tb++) {
                float2 kv = kr[tb * 32];
                s[tb] += qx * kv.x + qy * kv.y;
            }
        }

        // scale + relative-position bias
#pragma unroll
        for (int tb = 0; tb < NT; tb++) {
            int t = tb * 32 + lane;
            s[tb] = s[tb] * 0.125f + rbh[t - q + (S - 1)];
        }

        // softmax over S (held across lanes x NT regs)
        float mx = s[0];
#pragma unroll
        for (int tb = 1; tb < NT; tb++) mx = fmaxf(mx, s[tb]);
#pragma unroll
        for (int o = 16; o > 0; o >>= 1)
            mx = fmaxf(mx, __shfl_xor_sync(0xffffffffu, mx, o));
        float sum = 0.f;
#pragma unroll
        for (int tb = 0; tb < NT; tb++) { s[tb] = __expf(s[tb] - mx); sum += s[tb]; }
#pragma unroll
        for (int o = 16; o > 0; o >>= 1)
            sum += __shfl_xor_sync(0xffffffffu, sum, o);
        float inv = 1.f / sum;
#pragma unroll
        for (int tb = 0; tb < NT; tb++) s[tb] *= inv;

        // ctx = w @ V   (lane owns d = 2*lane, 2*lane+1)
        float cx = 0.f, cy = 0.f;
#pragma unroll
        for (int tb = 0; tb < NT; tb++) {
            float wv = s[tb];
#pragma unroll 8
            for (int j = 0; j < 32; j++) {
                float wj = __shfl_sync(0xffffffffu, wv, j);
                float2 vv = Vs2[(tb * 32 + j) * 32 + lane];
                cx += wj * vv.x;
                cy += wj * vv.y;
            }
        }
        float2 cw; cw.x = cx; cw.y = cy;
        *(float2*)&Ctx[qoff + 2 * lane] = cw;
    }
}

// ---------------------------------------------------------------------------
// Selection softmax over the token axis (8192) per (b, k), in place.
// grid: (B, KSEL/32), block 256 = 8 token-rows x 32 k-lanes. Coalesced.
// ---------------------------------------------------------------------------
__global__ __launch_bounds__(256)
void sel_softmax(float* __restrict__ sc)
{
    const int b = blockIdx.x;
    const int k0 = blockIdx.y * 32;
    const int lane = threadIdx.x & 31;
    const int row = threadIdx.x >> 5;

    float* base = sc + (size_t)b * MTOK_B * KSEL + k0 + lane;

    __shared__ float redA[8][32];
    __shared__ float redB[8][32];

    float mx = -1e30f;
    for (int m = row; m < MTOK_B; m += 8)
        mx = fmaxf(mx, base[(size_t)m * KSEL]);
    redA[row][lane] = mx;
    __syncthreads();
    if (row == 0) {
        float v = redA[0][lane];
#pragma unroll
        for (int r = 1; r < 8; r++) v = fmaxf(v, redA[r][lane]);
        redA[0][lane] = v;
    }
    __syncthreads();
    mx = redA[0][lane];

    float sum = 0.f;
    for (int m = row; m < MTOK_B; m += 8)
        sum += __expf(base[(size_t)m * KSEL] - mx);
    redB[row][lane] = sum;
    __syncthreads();
    if (row == 0) {
        float v = 0.f;
#pragma unroll
        for (int r = 0; r < 8; r++) v += redB[r][lane];
        redB[0][lane] = v;
    }
    __syncthreads();
    float inv = 1.f / redB[0][lane];

    for (int m = row; m < MTOK_B; m += 8) {
        float* p = &base[(size_t)m * KSEL];
        *p = __expf(*p - mx) * inv;
    }
}

// ---------------------------------------------------------------------------
// Multi-scale pooling: out[B][448][E] from sel[B][256][E]
// rows 0..255 = sel; 256..383 = pairwise mean; 384..447 = quad mean
// ---------------------------------------------------------------------------
__global__ void pool_kernel(const float* __restrict__ sel, float* __restrict__ out)
{
    int idx = blockIdx.x * blockDim.x + threadIdx.x;
    int total = B_DIM * OUT_ROWS * E_DIM;
    if (idx >= total) return;
    int e = idx % E_DIM;
    int r = (idx / E_DIM) % OUT_ROWS;
    int b = idx / (OUT_ROWS * E_DIM);
    const float* sb = sel + (size_t)b * KSEL * E_DIM;
    float v;
    if (r < 256) {
        v = sb[(size_t)r * E_DIM + e];
    } else if (r < 384) {
        int i = (r - 256) * 2;
        v = 0.5f * (sb[(size_t)i * E_DIM + e] + sb[(size_t)(i + 1) * E_DIM + e]);
    } else {
        int i = (r - 384) * 4;
        v = 0.25f * (sb[(size_t)i * E_DIM + e] + sb[(size_t)(i + 1) * E_DIM + e] +
                     sb[(size_t)(i + 2) * E_DIM + e] + sb[(size_t)(i + 3) * E_DIM + e]);
    }
    out[idx] = v;
}

// ---------------------------------------------------------------------------
// Orchestration
// ---------------------------------------------------------------------------
extern "C" void kernel_launch(void* const* d_in, const int* in_sizes, int n_in,
                              void* d_out, int out_size)
{
    (void)in_sizes; (void)n_in; (void)out_size;

    const float* x    = (const float*)d_in[0];
    const float* wq   = (const float*)d_in[1];
    const float* bq   = (const float*)d_in[2];
    const float* wk   = (const float*)d_in[3];
    const float* bk   = (const float*)d_in[4];
    const float* wv   = (const float*)d_in[5];
    const float* bv   = (const float*)d_in[6];
    const float* wd   = (const float*)d_in[7];
    const float* bd   = (const float*)d_in[8];
    const float* rb   = (const float*)d_in[9];
    const float* selw = (const float*)d_in[10];
    const float* selb = (const float*)d_in[11];
    float* out = (float*)d_out;

    float *Qb, *Kb, *Vb, *Cb, *Hb, *SCb, *SELb;
    cudaGetSymbolAddress((void**)&Qb,  g_Q);
    cudaGetSymbolAddress((void**)&Kb,  g_Kb);
    cudaGetSymbolAddress((void**)&Vb,  g_Vb);
    cudaGetSymbolAddress((void**)&Cb,  g_Cb);
    cudaGetSymbolAddress((void**)&Hb,  g_Hb);
    cudaGetSymbolAddress((void**)&SCb, g_SC);
    cudaGetSymbolAddress((void**)&SELb, g_SEL);

    // dynamic smem for spatial attention (> 48KB)
    const int smemSp = (32 * (256 + 1) * 2 + 256 * 32 * 2 + (2 * 256 - 1)) * (int)sizeof(float);
    const int smemTe = (32 * (32 + 1) * 2 + 32 * 32 * 2 + (2 * 32 - 1)) * (int)sizeof(float);
    cudaFuncSetAttribute((const void*)attn_kernel<256>,
                         cudaFuncAttributeMaxDynamicSharedMemorySize, smemSp);

    const dim3 gProj(E_DIM / 128, MTOK / 128);   // 8 x 128
    const dim3 blk(256);

    for (int a = 0; a < 4; a++) {
        const float* src = (a == 0) ? x : Hb;
        gemm_nn_bias<<<gProj, blk>>>(src, wq + (size_t)a * E_DIM * E_DIM, bq + a * E_DIM, Qb, MTOK, E_DIM, E_DIM);
        gemm_nn_bias<<<gProj, blk>>>(src, wk + (size_t)a * E_DIM * E_DIM, bk + a * E_DIM, Kb, MTOK, E_DIM, E_DIM);
        gemm_nn_bias<<<gProj, blk>>>(src, wv + (size_t)a * E_DIM * E_DIM, bv + a * E_DIM, Vb, MTOK, E_DIM, E_DIM);

        const float* rba = rb + (size_t)a * RB_ONE;
        if ((a & 1) == 0) {
            // spatial: 64 groups (b,t), S=256, base = g*256, step 1
            attn_kernel<256><<<dim3(H_DIM, B_DIM * T_DIM), blk, smemSp>>>(
                Qb, Kb, Vb, Cb, rba, /*div*/ B_DIM * T_DIM, /*mulq*/ 0, /*mulr*/ N_DIM, /*step*/ 1);
        } else {
            // temporal: 512 groups (b,n), S=32, base = b*8192 + n, step 256
            attn_kernel<32><<<dim3(H_DIM, B_DIM * N_DIM), blk, smemTe>>>(
                Qb, Kb, Vb, Cb, rba, /*div*/ N_DIM, /*mulq*/ T_DIM * N_DIM, /*mulr*/ 1, /*step*/ N_DIM);
        }

        gemm_nn_bias<<<gProj, blk>>>(Cb, wd + (size_t)a * E_DIM * E_DIM, bd + a * E_DIM, Hb, MTOK, E_DIM, E_DIM);
    }

    // selection scores: [MTOK, KSEL]
    gemm_nn_bias<<<dim3(KSEL / 128, MTOK / 128), blk>>>(Hb, selw, selb, SCb, MTOK, KSEL, E_DIM);

    // softmax over token axis per (b, k), in place
    sel_softmax<<<dim3(B_DIM, KSEL / 32), blk>>>(SCb);

    // sel[b,k,e] = sum_m wts[b,m,k] * h[b,m,e]  (split-K + atomics)
    cudaMemsetAsync(SELb, 0, (size_t)B_DIM * KSEL * E_DIM * sizeof(float));
    gemm_sel_atomic<<<dim3(E_DIM / 128, KSEL / 128, B_DIM * SPLITK), blk>>>(SCb, Hb, SELb);

    // multi-scale pooling -> output [B, 448, E]
    int total = B_DIM * OUT_ROWS * E_DIM;
    pool_kernel<<<(total + 255) / 256, 256>>>(SELb, out);
}

// round 3
// speedup vs baseline: 1.5679x; 1.5679x over previous
#include <cuda_runtime.h>
#include <cuda_bf16.h>
#include <cstdint>
#include <cstddef>

// ---------------------------------------------------------------------------
// Problem constants
// ---------------------------------------------------------------------------
#define E_DIM   1024
#define H_DIM   16
#define D_DIM   64
#define B_DIM   2
#define T_DIM   32
#define N_DIM   256
#define MTOK    (B_DIM * T_DIM * N_DIM)   // 16384 tokens total
#define MTOK_B  (T_DIM * N_DIM)           // 8192 tokens per batch
#define KSEL    256
#define MAXLEN  512
#define RB_ONE  ((2 * MAXLEN - 1) * H_DIM)
#define SPLITK  8
#define OUT_ROWS 448                      // 256 + 128 + 64

// ---------------------------------------------------------------------------
// Scratch (device globals — no allocations allowed)
// ---------------------------------------------------------------------------
__device__ float g_Q[MTOK * E_DIM];
__device__ float g_Kb[MTOK * E_DIM];
__device__ float g_Vb[MTOK * E_DIM];
__device__ float g_Cb[MTOK * E_DIM];
__device__ float g_Hb[MTOK * E_DIM];
__device__ float g_SC[MTOK * KSEL];
__device__ float g_SEL[B_DIM * KSEL * E_DIM];

// bf16 split activations (reused across layers)
__device__ __nv_bfloat16 g_Ah[MTOK * E_DIM];
__device__ __nv_bfloat16 g_Al[MTOK * E_DIM];
// transposed + split weights: [type][a][N=E][K=E]
__device__ __nv_bfloat16 g_WqTh[4 * E_DIM * E_DIM];
__device__ __nv_bfloat16 g_WqTl[4 * E_DIM * E_DIM];
__device__ __nv_bfloat16 g_WkTh[4 * E_DIM * E_DIM];
__device__ __nv_bfloat16 g_WkTl[4 * E_DIM * E_DIM];
__device__ __nv_bfloat16 g_WvTh[4 * E_DIM * E_DIM];
__device__ __nv_bfloat16 g_WvTl[4 * E_DIM * E_DIM];
__device__ __nv_bfloat16 g_WdTh[4 * E_DIM * E_DIM];
__device__ __nv_bfloat16 g_WdTl[4 * E_DIM * E_DIM];
__device__ __nv_bfloat16 g_SWTh[KSEL * E_DIM];
__device__ __nv_bfloat16 g_SWTl[KSEL * E_DIM];

// ---------------------------------------------------------------------------
// PTX helpers (cp.async / ldmatrix / mma.sync — all baseline sm_80+ PTX)
// ---------------------------------------------------------------------------
__device__ __forceinline__ void cp_async16(uint32_t dst, const void* src) {
    asm volatile("cp.async.cg.shared.global [%0], [%1], 16;" :: "r"(dst), "l"(src));
}
__device__ __forceinline__ void cp_commit() {
    asm volatile("cp.async.commit_group;" ::: "memory");
}
template <int N>
__device__ __forceinline__ void cp_wait_group() {
    asm volatile("cp.async.wait_group %0;" :: "n"(N) : "memory");
}
__device__ __forceinline__ void ldmatrix_x4(uint32_t* r, uint32_t addr) {
    asm volatile("ldmatrix.sync.aligned.m8n8.x4.shared.b16 {%0,%1,%2,%3}, [%4];"
                 : "=r"(r[0]), "=r"(r[1]), "=r"(r[2]), "=r"(r[3]) : "r"(addr));
}
__device__ __forceinline__ void mma_bf16(float* d, const uint32_t* a,
                                         uint32_t b0, uint32_t b1) {
    asm volatile(
        "mma.sync.aligned.m16n8k16.row.col.f32.bf16.bf16.f32 "
        "{%0,%1,%2,%3}, {%4,%5,%6,%7}, {%8,%9}, {%0,%1,%2,%3};"
        : "+f"(d[0]), "+f"(d[1]), "+f"(d[2]), "+f"(d[3])
        : "r"(a[0]), "r"(a[1]), "r"(a[2]), "r"(a[3]), "r"(b0), "r"(b1));
}

// ---------------------------------------------------------------------------
// bf16x3 GEMM via mma.sync:
//   C[M, Nfull] = (Ah+Al)[M,K] @ (Bh+Bl)[Nfull,K]^T + bias
// 3-term split folded into mainloop: seg0 Ah*Bh, seg1 Al*Bh, seg2 Ah*Bl.
// CTA 128x128, k-chunk 32 bf16, 4-stage cp.async pipeline.
// 8 warps (4 in M x 2 in N), warp tile 32x64, m16n8k16.
// SMEM rows padded to 40 elems (80B) -> conflict-free ldmatrix.
// ---------------------------------------------------------------------------
#define GSTAGES 4
#define ROWPAD  40                          // 32 data + 8 pad elems (bf16)
#define TILE_BYTES (128 * ROWPAD * 2)       // 10240 per operand per stage
#define GEMM_SMEM (GSTAGES * 2 * TILE_BYTES) // 81920

__global__ __launch_bounds__(256, 2)
void gemm_bf16x3(const __nv_bfloat16* __restrict__ Ah, const __nv_bfloat16* __restrict__ Al,
                 const __nv_bfloat16* __restrict__ Bh, const __nv_bfloat16* __restrict__ Bl,
                 const float* __restrict__ bias, float* __restrict__ C,
                 int Nfull, int Kfull)
{
    extern __shared__ char smem[];
    const uint32_t sb = (uint32_t)__cvta_generic_to_shared(smem);
    const int tid = threadIdx.x;
    const int lane = tid & 31;
    const int warp = tid >> 5;
    const int wm = warp >> 1;          // 0..3 -> m offset wm*32
    const int wn = warp & 1;           // 0..1 -> n offset wn*64
    const int m0 = blockIdx.y * 128;
    const int n0 = blockIdx.x * 128;

    const int kch = Kfull >> 5;        // chunks per segment
    const int NCH = 3 * kch;

    // per-thread load slots: 512 cp.async16 per operand tile, 2 per thread
    const int lr0 = tid >> 1;                  // row for slot 0 (0..127)
    const int ls0 = (tid & 1) << 1;            // seg4 0 or 2
    // slot j: row lr0, seg ls0 + j  (j = 0,1)

    float acc[2][8][4];
#pragma unroll
    for (int mi = 0; mi < 2; mi++)
#pragma unroll
        for (int ni = 0; ni < 8; ni++)
#pragma unroll
            for (int q = 0; q < 4; q++) acc[mi][ni][q] = 0.f;

    auto load_chunk = [&](int c, int stage) {
        const int seg = c / kch;
        const int kb = (c - seg * kch) << 5;
        const __nv_bfloat16* Ap = (seg == 1) ? Al : Ah;
        const __nv_bfloat16* Bp = (seg == 2) ? Bl : Bh;
        const uint32_t Abase = sb + stage * TILE_BYTES;
        const uint32_t Bbase = sb + GSTAGES * TILE_BYTES + stage * TILE_BYTES;
#pragma unroll
        for (int j = 0; j < 2; j++) {
            const int r = lr0;
            const int s4 = ls0 + j;
            const uint32_t soff = (uint32_t)(r * ROWPAD + s4 * 8) * 2;
            cp_async16(Abase + soff, Ap + (size_t)(m0 + r) * Kfull + kb + s4 * 8);
            cp_async16(Bbase + soff, Bp + (size_t)(n0 + r) * Kfull + kb + s4 * 8);
        }
    };

    // prologue: prefetch GSTAGES-1 chunks
#pragma unroll
    for (int s = 0; s < GSTAGES - 1; s++) {
        if (s < NCH) load_chunk(s, s);
        cp_commit();
    }

    // ldmatrix lane addressing (within a stage tile)
    const int la_i = lane & 7;
    const int la_g = lane >> 3;
    // A: row = mrow + (g&1)*8, col = k16 + (g>>1)*8
    const int a_rowadd = la_i + ((la_g & 1) << 3);
    const int a_coladd = (la_g >> 1) << 3;
    // B: row = nrow + (g>>1)*8, col = k16 + (g&1)*8
    const int b_rowadd = la_i + ((la_g >> 1) << 3);
    const int b_coladd = (la_g & 1) << 3;

    for (int c = 0; c < NCH; c++) {
        const int stage = c & (GSTAGES - 1);
        cp_wait_group<GSTAGES - 2>();
        __syncthreads();

        const int nc = c + GSTAGES - 1;
        if (nc < NCH) load_chunk(nc, nc & (GSTAGES - 1));
        cp_commit();

        const uint32_t Abase = sb + stage * TILE_BYTES;
        const uint32_t Bbase = sb + GSTAGES * TILE_BYTES + stage * TILE_BYTES;

#pragma unroll
        for (int k16 = 0; k16 < 32; k16 += 16) {
            uint32_t af[2][4];
#pragma unroll
            for (int mi = 0; mi < 2; mi++) {
                const int row = wm * 32 + mi * 16 + a_rowadd;
                const int col = k16 + a_coladd;
                ldmatrix_x4(af[mi], Abase + (uint32_t)(row * ROWPAD + col) * 2);
            }
#pragma unroll
            for (int nb = 0; nb < 4; nb++) {
                uint32_t bf[4];
                const int row = wn * 64 + nb * 16 + b_rowadd;
                const int col = k16 + b_coladd;
                ldmatrix_x4(bf, Bbase + (uint32_t)(row * ROWPAD + col) * 2);
#pragma unroll
                for (int mi = 0; mi < 2; mi++) {
                    mma_bf16(acc[mi][nb * 2 + 0], af[mi], bf[0], bf[1]);
                    mma_bf16(acc[mi][nb * 2 + 1], af[mi], bf[2], bf[3]);
                }
            }
        }
    }

    // epilogue
    const int tq = lane >> 2;
    const int tr = lane & 3;
#pragma unroll
    for (int mi = 0; mi < 2; mi++) {
        const int row = m0 + wm * 32 + mi * 16 + tq;
#pragma unroll
        for (int ni = 0; ni < 8; ni++) {
            const int col = n0 + wn * 64 + ni * 8 + tr * 2;
            const float b0 = bias[col], b1 = bias[col + 1];
            float2 v0, v1;
            v0.x = acc[mi][ni][0] + b0; v0.y = acc[mi][ni][1] + b1;
            v1.x = acc[mi][ni][2] + b0; v1.y = acc[mi][ni][3] + b1;
            *(float2*)&C[(size_t)row * Nfull + col] = v0;
            *(float2*)&C[(size_t)(row + 8) * Nfull + col] = v1;
        }
    }
}

// ---------------------------------------------------------------------------
// fp32 -> bf16 hi/lo split (elementwise, float4 vectorized)
// ---------------------------------------------------------------------------
__global__ void cvt_hilo(const float* __restrict__ x, __nv_bfloat16* __restrict__ hi,
                         __nv_bfloat16* __restrict__ lo, int n4)
{
    int i = blockIdx.x * blockDim.x + threadIdx.x;
    if (i >= n4) return;
    float4 v = ((const float4*)x)[i];
    __nv_bfloat16 h0 = __float2bfloat16(v.x);
    __nv_bfloat16 h1 = __float2bfloat16(v.y);
    __nv_bfloat16 h2 = __float2bfloat16(v.z);
    __nv_bfloat16 h3 = __float2bfloat16(v.w);
    __nv_bfloat16 l0 = __float2bfloat16(v.x - __bfloat162float(h0));
    __nv_bfloat16 l1 = __float2bfloat16(v.y - __bfloat162float(h1));
    __nv_bfloat16 l2 = __float2bfloat16(v.z - __bfloat162float(h2));
    __nv_bfloat16 l3 = __float2bfloat16(v.w - __bfloat162float(h3));
    __nv_bfloat162* hp = (__nv_bfloat162*)hi;
    __nv_bfloat162* lp = (__nv_bfloat162*)lo;
    hp[2 * i + 0] = __nv_bfloat162(h0, h1);
    hp[2 * i + 1] = __nv_bfloat162(h2, h3);
    lp[2 * i + 0] = __nv_bfloat162(l0, l1);
    lp[2 * i + 1] = __nv_bfloat162(l2, l3);
}

// ---------------------------------------------------------------------------
// Weight transpose + hi/lo split:  W[z][Kd][Nd] fp32 -> WT hi/lo [z][Nd][Kd]
// ---------------------------------------------------------------------------
__global__ void wt_cvt(const float* __restrict__ W, __nv_bfloat16* __restrict__ WTh,
                       __nv_bfloat16* __restrict__ WTl, int Kd, int Nd)
{
    __shared__ float t[32][33];
    const size_t moff = (size_t)blockIdx.z * Kd * Nd;
    const float* Wm = W + moff;
    __nv_bfloat16* Hh = WTh + moff;
    __nv_bfloat16* Hl = WTl + moff;

    int nx = blockIdx.x * 32 + threadIdx.x;
    int k0 = blockIdx.y * 32;
#pragma unroll
    for (int j = 0; j < 4; j++) {
        int kk = k0 + threadIdx.y + j * 8;
        t[threadIdx.y + j * 8][threadIdx.x] = Wm[(size_t)kk * Nd + nx];
    }
    __syncthreads();
    int kx = k0 + threadIdx.x;
#pragma unroll
    for (int j = 0; j < 4; j++) {
        int nn = blockIdx.x * 32 + threadIdx.y + j * 8;
        float v = t[threadIdx.x][threadIdx.y + j * 8];
        __nv_bfloat16 h = __float2bfloat16(v);
        __nv_bfloat16 l = __float2bfloat16(v - __bfloat162float(h));
        Hh[(size_t)nn * Kd + kx] = h;
        Hl[(size_t)nn * Kd + kx] = l;
    }
}

// ---------------------------------------------------------------------------
// Split-K pooled-selection GEMM (fp32, atomics)
// ---------------------------------------------------------------------------
__global__ __launch_bounds__(256, 2)
void gemm_sel_atomic(const float* __restrict__ Wts, const float* __restrict__ Flat,
                     float* __restrict__ Csel)
{
    __shared__ float As[16][128];
    __shared__ float Bs[16][128];

    const int tid = threadIdx.x;
    const int bx = blockIdx.x;
    const int by = blockIdx.y;
    const int b  = blockIdx.z / SPLITK;
    const int sl = blockIdx.z % SPLITK;

    const float* A = Wts  + (size_t)b * MTOK_B * KSEL;
    const float* B = Flat + (size_t)b * MTOK_B * E_DIM;
    float*       C = Csel + (size_t)b * KSEL * E_DIM;

    const int lr = (tid & 31) << 2;
    const int lk = tid >> 5;
    const int tx = tid & 15;
    const int ty = tid >> 4;

    const int kbeg = sl * (MTOK_B / SPLITK);
    const int kend = kbeg + (MTOK_B / SPLITK);

    float acc[8][8];
#pragma unroll
    for (int i = 0; i < 8; i++)
#pragma unroll
        for (int j = 0; j < 8; j++) acc[i][j] = 0.f;

    for (int k0 = kbeg; k0 < kend; k0 += 16) {
        *(float4*)&As[lk][lr]     = *(const float4*)&A[(size_t)(k0 + lk) * KSEL + by * 128 + lr];
        *(float4*)&As[lk + 8][lr] = *(const float4*)&A[(size_t)(k0 + lk + 8) * KSEL + by * 128 + lr];
        *(float4*)&Bs[lk][lr]     = *(const float4*)&B[(size_t)(k0 + lk) * E_DIM + bx * 128 + lr];
        *(float4*)&Bs[lk + 8][lr] = *(const float4*)&B[(size_t)(k0 + lk + 8) * E_DIM + bx * 128 + lr];
        __syncthreads();

#pragma unroll
        for (int kk = 0; kk < 16; kk++) {
            float ar[8], br[8];
            *(float4*)&ar[0] = *(const float4*)&As[kk][ty * 8];
            *(float4*)&ar[4] = *(const float4*)&As[kk][ty * 8 + 4];
            *(float4*)&br[0] = *(const float4*)&Bs[kk][tx * 8];
            *(float4*)&br[4] = *(const float4*)&Bs[kk][tx * 8 + 4];
#pragma unroll
            for (int i = 0; i < 8; i++)
#pragma unroll
                for (int j = 0; j < 8; j++)
                    acc[i][j] += ar[i] * br[j];
        }
        __syncthreads();
    }

#pragma unroll
    for (int i = 0; i < 8; i++) {
        float* cp = C + (size_t)(by * 128 + ty * 8 + i) * E_DIM + bx * 128 + tx * 8;
#pragma unroll
        for (int j = 0; j < 8; j++)
            atomicAdd(&cp[j], acc[i][j]);
    }
}

// ---------------------------------------------------------------------------
// Fused relative-bias multihead attention
// ---------------------------------------------------------------------------
template <int S>
__global__ __launch_bounds__(256)
void attn_kernel(const float* __restrict__ Q, const float* __restrict__ K,
                 const float* __restrict__ V, float* __restrict__ Ctx,
                 const float* __restrict__ rb,
                 int div, int mulq, int mulr, int stepTok)
{
    const int h = blockIdx.x;
    const int g = blockIdx.y;
    const int base_m = (g / div) * mulq + (g % div) * mulr;
    const size_t baseE = (size_t)base_m * E_DIM + h * D_DIM;
    const size_t stepE = (size_t)stepTok * E_DIM;

    extern __shared__ float sm[];
    float2* Kt2 = (float2*)sm;
    float2* Vs2 = Kt2 + 32 * (S + 1);
    float*  rbh = (float*)(Vs2 + S * 32);

    const int tid = threadIdx.x;

    for (int idx = tid; idx < S * 32; idx += 256) {
        int t = idx >> 5, d2 = idx & 31;
        size_t off = baseE + (size_t)t * stepE;
        Kt2[d2 * (S + 1) + t] = *(const float2*)&K[off + 2 * d2];
        Vs2[idx]              = *(const float2*)&V[off + 2 * d2];
    }
    for (int i = tid; i < 2 * S - 1; i += 256)
        rbh[i] = rb[(size_t)(MAXLEN - S + i) * H_DIM + h];
    __syncthreads();

    const int lane = tid & 31;
    const int warp = tid >> 5;
    const int NT = S / 32;

    for (int q = warp; q < S; q += 8) {
        size_t qoff = baseE + (size_t)q * stepE;
        float2 ql = *(const float2*)&Q[qoff + 2 * lane];

        float s[NT];
#pragma unroll
        for (int tb = 0; tb < NT; tb++) s[tb] = 0.f;

#pragma unroll 4
        for (int d2 = 0; d2 < 32; d2++) {
            float qx = __shfl_sync(0xffffffffu, ql.x, d2);
            float qy = __shfl_sync(0xffffffffu, ql.y, d2);
            const float2* kr = &Kt2[d2 * (S + 1) + lane];
#pragma unroll
            for (int tb = 0; tb < NT; tb++) {
                float2 kv = kr[tb * 32];
                s[tb] += qx * kv.x + qy * kv.y;
            }
        }

#pragma unroll
        for (int tb = 0; tb < NT; tb++) {
            int t = tb * 32 + lane;
            s[tb] = s[tb] * 0.125f + rbh[t - q + (S - 1)];
        }

        float mx = s[0];
#pragma unroll
        for (int tb = 1; tb < NT; tb++) mx = fmaxf(mx, s[tb]);
#pragma unroll
        for (int o = 16; o > 0; o >>= 1)
            mx = fmaxf(mx, __shfl_xor_sync(0xffffffffu, mx, o));
        float sum = 0.f;
#pragma unroll
        for (int tb = 0; tb < NT; tb++) { s[tb] = __expf(s[tb] - mx); sum += s[tb]; }
#pragma unroll
        for (int o = 16; o > 0; o >>= 1)
            sum += __shfl_xor_sync(0xffffffffu, sum, o);
        float inv = 1.f / sum;
#pragma unroll
        for (int tb = 0; tb < NT; tb++) s[tb] *= inv;

        float cx = 0.f, cy = 0.f;
#pragma unroll
        for (int tb = 0; tb < NT; tb++) {
            float wv = s[tb];
#pragma unroll 8
            for (int j = 0; j < 32; j++) {
                float wj = __shfl_sync(0xffffffffu, wv, j);
                float2 vv = Vs2[(tb * 32 + j) * 32 + lane];
                cx += wj * vv.x;
                cy += wj * vv.y;
            }
        }
        float2 cw; cw.x = cx; cw.y = cy;
        *(float2*)&Ctx[qoff + 2 * lane] = cw;
    }
}

// ---------------------------------------------------------------------------
// Selection softmax over token axis per (b, k), in place
// ---------------------------------------------------------------------------
__global__ __launch_bounds__(256)
void sel_softmax(float* __restrict__ sc)
{
    const int b = blockIdx.x;
    const int k0 = blockIdx.y * 32;
    const int lane = threadIdx.x & 31;
    const int row = threadIdx.x >> 5;

    float* base = sc + (size_t)b * MTOK_B * KSEL + k0 + lane;

    __shared__ float redA[8][32];
    __shared__ float redB[8][32];

    float mx = -1e30f;
    for (int m = row; m < MTOK_B; m += 8)
        mx = fmaxf(mx, base[(size_t)m * KSEL]);
    redA[row][lane] = mx;
    __syncthreads();
    if (row == 0) {
        float v = redA[0][lane];
#pragma unroll
        for (int r = 1; r < 8; r++) v = fmaxf(v, redA[r][lane]);
        redA[0][lane] = v;
    }
    __syncthreads();
    mx = redA[0][lane];

    float sum = 0.f;
    for (int m = row; m < MTOK_B; m += 8)
        sum += __expf(base[(size_t)m * KSEL] - mx);
    redB[row][lane] = sum;
    __syncthreads();
    if (row == 0) {
        float v = 0.f;
#pragma unroll
        for (int r = 0; r < 8; r++) v += redB[r][lane];
        redB[0][lane] = v;
    }
    __syncthreads();
    float inv = 1.f / redB[0][lane];

    for (int m = row; m < MTOK_B; m += 8) {
        float* p = &base[(size_t)m * KSEL];
        *p = __expf(*p - mx) * inv;
    }
}

// ---------------------------------------------------------------------------
// Multi-scale pooling
// ---------------------------------------------------------------------------
__global__ void pool_kernel(const float* __restrict__ sel, float* __restrict__ out)
{
    int idx = blockIdx.x * blockDim.x + threadIdx.x;
    int total = B_DIM * OUT_ROWS * E_DIM;
    if (idx >= total) return;
    int e = idx % E_DIM;
    int r = (idx / E_DIM) % OUT_ROWS;
    int b = idx / (OUT_ROWS * E_DIM);
    const float* sb = sel + (size_t)b * KSEL * E_DIM;
    float v;
    if (r < 256) {
        v = sb[(size_t)r * E_DIM + e];
    } else if (r < 384) {
        int i = (r - 256) * 2;
        v = 0.5f * (sb[(size_t)i * E_DIM + e] + sb[(size_t)(i + 1) * E_DIM + e]);
    } else {
        int i = (r - 384) * 4;
        v = 0.25f * (sb[(size_t)i * E_DIM + e] + sb[(size_t)(i + 1) * E_DIM + e] +
                     sb[(size_t)(i + 2) * E_DIM + e] + sb[(size_t)(i + 3) * E_DIM + e]);
    }
    out[idx] = v;
}

// ---------------------------------------------------------------------------
// Orchestration
// ---------------------------------------------------------------------------
extern "C" void kernel_launch(void* const* d_in, const int* in_sizes, int n_in,
                              void* d_out, int out_size)
{
    (void)in_sizes; (void)n_in; (void)out_size;

    const float* x    = (const float*)d_in[0];
    const float* wq   = (const float*)d_in[1];
    const float* bq   = (const float*)d_in[2];
    const float* wk   = (const float*)d_in[3];
    const float* bk   = (const float*)d_in[4];
    const float* wv   = (const float*)d_in[5];
    const float* bv   = (const float*)d_in[6];
    const float* wd   = (const float*)d_in[7];
    const float* bd   = (const float*)d_in[8];
    const float* rb   = (const float*)d_in[9];
    const float* selw = (const float*)d_in[10];
    const float* selb = (const float*)d_in[11];
    float* out = (float*)d_out;

    float *Qb, *Kb, *Vb, *Cb, *Hb, *SCb, *SELb;
    cudaGetSymbolAddress((void**)&Qb,  g_Q);
    cudaGetSymbolAddress((void**)&Kb,  g_Kb);
    cudaGetSymbolAddress((void**)&Vb,  g_Vb);
    cudaGetSymbolAddress((void**)&Cb,  g_Cb);
    cudaGetSymbolAddress((void**)&Hb,  g_Hb);
    cudaGetSymbolAddress((void**)&SCb, g_SC);
    cudaGetSymbolAddress((void**)&SELb, g_SEL);

    __nv_bfloat16 *Ahp, *Alp;
    __nv_bfloat16 *WqTh, *WqTl, *WkTh, *WkTl, *WvTh, *WvTl, *WdTh, *WdTl, *SWTh, *SWTl;
    cudaGetSymbolAddress((void**)&Ahp, g_Ah);
    cudaGetSymbolAddress((void**)&Alp, g_Al);
    cudaGetSymbolAddress((void**)&WqTh, g_WqTh);
    cudaGetSymbolAddress((void**)&WqTl, g_WqTl);
    cudaGetSymbolAddress((void**)&WkTh, g_WkTh);
    cudaGetSymbolAddress((void**)&WkTl, g_WkTl);
    cudaGetSymbolAddress((void**)&WvTh, g_WvTh);
    cudaGetSymbolAddress((void**)&WvTl, g_WvTl);
    cudaGetSymbolAddress((void**)&WdTh, g_WdTh);
    cudaGetSymbolAddress((void**)&WdTl, g_WdTl);
    cudaGetSymbolAddress((void**)&SWTh, g_SWTh);
    cudaGetSymbolAddress((void**)&SWTl, g_SWTl);

    const int smemSp = (32 * (256 + 1) * 2 + 256 * 32 * 2 + (2 * 256 - 1)) * (int)sizeof(float);
    const int smemTe = (32 * (32 + 1) * 2 + 32 * 32 * 2 + (2 * 32 - 1)) * (int)sizeof(float);
    cudaFuncSetAttribute((const void*)attn_kernel<256>,
                         cudaFuncAttributeMaxDynamicSharedMemorySize, smemSp);
    cudaFuncSetAttribute((const void*)gemm_bf16x3,
                         cudaFuncAttributeMaxDynamicSharedMemorySize, GEMM_SMEM);

    const dim3 blk(256);
    const dim3 tblk(32, 8);

    // weight transpose + split (once per call)
    wt_cvt<<<dim3(E_DIM / 32, E_DIM / 32, 4), tblk>>>(wq, WqTh, WqTl, E_DIM, E_DIM);
    wt_cvt<<<dim3(E_DIM / 32, E_DIM / 32, 4), tblk>>>(wk, WkTh, WkTl, E_DIM, E_DIM);
    wt_cvt<<<dim3(E_DIM / 32, E_DIM / 32, 4), tblk>>>(wv, WvTh, WvTl, E_DIM, E_DIM);
    wt_cvt<<<dim3(E_DIM / 32, E_DIM / 32, 4), tblk>>>(wd, WdTh, WdTl, E_DIM, E_DIM);
    wt_cvt<<<dim3(KSEL / 32, E_DIM / 32, 1), tblk>>>(selw, SWTh, SWTl, E_DIM, KSEL);

    const int n4 = MTOK * E_DIM / 4;
    const dim3 gcvt((n4 + 255) / 256);
    const dim3 gProj(E_DIM / 128, MTOK / 128);    // 8 x 128 CTAs
    const size_t MM = (size_t)E_DIM * E_DIM;

    for (int a = 0; a < 4; a++) {
        const float* src = (a == 0) ? x : Hb;
        cvt_hilo<<<gcvt, blk>>>(src, Ahp, Alp, n4);
        gemm_bf16x3<<<gProj, blk, GEMM_SMEM>>>(Ahp, Alp, WqTh + a * MM, WqTl + a * MM, bq + a * E_DIM, Qb, E_DIM, E_DIM);
        gemm_bf16x3<<<gProj, blk, GEMM_SMEM>>>(Ahp, Alp, WkTh + a * MM, WkTl + a * MM, bk + a * E_DIM, Kb, E_DIM, E_DIM);
        gemm_bf16x3<<<gProj, blk, GEMM_SMEM>>>(Ahp, Alp, WvTh + a * MM, WvTl + a * MM, bv + a * E_DIM, Vb, E_DIM, E_DIM);

        const float* rba = rb + (size_t)a * RB_ONE;
        if ((a & 1) == 0) {
            attn_kernel<256><<<dim3(H_DIM, B_DIM * T_DIM), blk, smemSp>>>(
                Qb, Kb, Vb, Cb, rba, B_DIM * T_DIM, 0, N_DIM, 1);
        } else {
            attn_kernel<32><<<dim3(H_DIM, B_DIM * N_DIM), blk, smemTe>>>(
                Qb, Kb, Vb, Cb, rba, N_DIM, T_DIM * N_DIM, 1, N_DIM);
        }

        cvt_hilo<<<gcvt, blk>>>(Cb, Ahp, Alp, n4);
        gemm_bf16x3<<<gProj, blk, GEMM_SMEM>>>(Ahp, Alp, WdTh + a * MM, WdTl + a * MM, bd + a * E_DIM, Hb, E_DIM, E_DIM);
    }

    // selection scores: [MTOK, KSEL]
    cvt_hilo<<<gcvt, blk>>>(Hb, Ahp, Alp, n4);
    gemm_bf16x3<<<dim3(KSEL / 128, MTOK / 128), blk, GEMM_SMEM>>>(Ahp, Alp, SWTh, SWTl, selb, SCb, KSEL, E_DIM);

    // softmax over token axis per (b, k), in place
    sel_softmax<<<dim3(B_DIM, KSEL / 32), blk>>>(SCb);

    // sel[b,k,e] = sum_m wts[b,m,k] * h[b,m,e]  (split-K + atomics)
    cudaMemsetAsync(SELb, 0, (size_t)B_DIM * KSEL * E_DIM * sizeof(float));
    gemm_sel_atomic<<<dim3(E_DIM / 128, KSEL / 128, B_DIM * SPLITK), blk>>>(SCb, Hb, SELb);

    // multi-scale pooling -> output [B, 448, E]
    int total = B_DIM * OUT_ROWS * E_DIM;
    pool_kernel<<<(total + 255) / 256, 256>>>(SELb, out);
}

// round 4
// speedup vs baseline: 2.1606x; 1.3780x over previous
#include <cuda_runtime.h>
#include <cuda_fp16.h>
#include <cstdint>
#include <cstddef>

// ---------------------------------------------------------------------------
// Problem constants
// ---------------------------------------------------------------------------
#define E_DIM   1024
#define H_DIM   16
#define D_DIM   64
#define B_DIM   2
#define T_DIM   32
#define N_DIM   256
#define MTOK    (B_DIM * T_DIM * N_DIM)   // 16384 tokens total
#define MTOK_B  (T_DIM * N_DIM)           // 8192 tokens per batch
#define KSEL    256
#define MAXLEN  512
#define RB_ONE  ((2 * MAXLEN - 1) * H_DIM)
#define SPLITK  8
#define OUT_ROWS 448                      // 256 + 128 + 64

// ---------------------------------------------------------------------------
// Scratch (device globals — no allocations allowed)
// ---------------------------------------------------------------------------
__device__ float g_Q[MTOK * E_DIM];
__device__ float g_Kb[MTOK * E_DIM];
__device__ float g_Vb[MTOK * E_DIM];
__device__ float g_Cb[MTOK * E_DIM];
__device__ float g_Hb[MTOK * E_DIM];
__device__ float g_SC[MTOK * KSEL];
__device__ float g_SEL[B_DIM * KSEL * E_DIM];

// fp16 split activations (hi + lo), reused across layers
__device__ __half g_Ah[MTOK * E_DIM];
__device__ __half g_Al[MTOK * E_DIM];
// transposed fp16 weights: [a][N=E][K=E]
__device__ __half g_WqT[4 * E_DIM * E_DIM];
__device__ __half g_WkT[4 * E_DIM * E_DIM];
__device__ __half g_WvT[4 * E_DIM * E_DIM];
__device__ __half g_WdT[4 * E_DIM * E_DIM];
__device__ __half g_SWT[KSEL * E_DIM];

// ---------------------------------------------------------------------------
// PTX helpers (cp.async / ldmatrix / mma.sync — baseline sm_80+ PTX)
// ---------------------------------------------------------------------------
__device__ __forceinline__ void cp_async16(uint32_t dst, const void* src) {
    asm volatile("cp.async.cg.shared.global [%0], [%1], 16;" :: "r"(dst), "l"(src));
}
__device__ __forceinline__ void cp_commit() {
    asm volatile("cp.async.commit_group;" ::: "memory");
}
template <int N>
__device__ __forceinline__ void cp_wait_group() {
    asm volatile("cp.async.wait_group %0;" :: "n"(N) : "memory");
}
__device__ __forceinline__ void ldmatrix_x4(uint32_t* r, uint32_t addr) {
    asm volatile("ldmatrix.sync.aligned.m8n8.x4.shared.b16 {%0,%1,%2,%3}, [%4];"
                 : "=r"(r[0]), "=r"(r[1]), "=r"(r[2]), "=r"(r[3]) : "r"(addr));
}
__device__ __forceinline__ void mma_f16(float* d, const uint32_t* a,
                                        uint32_t b0, uint32_t b1) {
    asm volatile(
        "mma.sync.aligned.m16n8k16.row.col.f32.f16.f16.f32 "
        "{%0,%1,%2,%3}, {%4,%5,%6,%7}, {%8,%9}, {%0,%1,%2,%3};"
        : "+f"(d[0]), "+f"(d[1]), "+f"(d[2]), "+f"(d[3])
        : "r"(a[0]), "r"(a[1]), "r"(a[2]), "r"(a[3]), "r"(b0), "r"(b1));
}

// ---------------------------------------------------------------------------
// fp16x2 GEMM via mma.sync:
//   C[M, Nfull] = (Ah+Al)[M,K] @ B[Nfull,K]^T + bias
// A split fp16 hi/lo (exact to ~2^-24); B single fp16 (weights).
// Both segments accumulate into the same fp32 acc; B fragments in registers
// are reused across segments (B tile loaded ONCE per k-chunk).
// CTA 128x128, k-chunk 32, 3-stage cp.async pipeline (3 tiles/stage).
// 8 warps (4 in M x 2 in N), warp tile 32x64, m16n8k16.
// SMEM rows padded to 40 elems (80B) -> conflict-free ldmatrix.
// ---------------------------------------------------------------------------
#define GSTAGES 3
#define ROWPAD  40
#define TILE_BYTES (128 * ROWPAD * 2)         // 10240 per tile
#define STAGE_BYTES (3 * TILE_BYTES)          // Ah, Al, B
#define GEMM_SMEM (GSTAGES * STAGE_BYTES)     // 92160

__global__ __launch_bounds__(256, 2)
void gemm_f16x2(const __half* __restrict__ Ah, const __half* __restrict__ Al,
                const __half* __restrict__ B,
                const float* __restrict__ bias, float* __restrict__ C,
                int Nfull, int Kfull)
{
    extern __shared__ char smem[];
    const uint32_t sb = (uint32_t)__cvta_generic_to_shared(smem);
    const int tid = threadIdx.x;
    const int lane = tid & 31;
    const int warp = tid >> 5;
    const int wm = warp >> 1;          // 0..3 -> m offset wm*32
    const int wn = warp & 1;           // 0..1 -> n offset wn*64
    const int m0 = blockIdx.y * 128;
    const int n0 = blockIdx.x * 128;

    const int NCH = Kfull >> 5;        // k-chunks of 32

    const int lr0 = tid >> 1;          // row (0..127)
    const int ls0 = (tid & 1) << 1;    // 16B-segment base (0 or 2)

    float acc[2][8][4];
#pragma unroll
    for (int mi = 0; mi < 2; mi++)
#pragma unroll
        for (int ni = 0; ni < 8; ni++)
#pragma unroll
            for (int q = 0; q < 4; q++) acc[mi][ni][q] = 0.f;

    auto load_chunk = [&](int c, int stage) {
        const int kb = c << 5;
        const uint32_t base = sb + stage * STAGE_BYTES;
#pragma unroll
        for (int j = 0; j < 2; j++) {
            const int s4 = ls0 + j;
            const uint32_t soff = (uint32_t)(lr0 * ROWPAD + s4 * 8) * 2;
            const size_t goff = (size_t)lr0 * Kfull + kb + s4 * 8;
            cp_async16(base + soff,                  Ah + (size_t)m0 * Kfull + goff);
            cp_async16(base + TILE_BYTES + soff,     Al + (size_t)m0 * Kfull + goff);
            cp_async16(base + 2 * TILE_BYTES + soff, B  + (size_t)n0 * Kfull + goff);
        }
    };

    // prologue: prefetch 2 chunks
#pragma unroll
    for (int s = 0; s < GSTAGES - 1; s++) {
        if (s < NCH) load_chunk(s, s);
        cp_commit();
    }

    // ldmatrix lane addressing
    const int la_i = lane & 7;
    const int la_g = lane >> 3;
    const int a_rowadd = la_i + ((la_g & 1) << 3);
    const int a_coladd = (la_g >> 1) << 3;
    const int b_rowadd = la_i + ((la_g >> 1) << 3);
    const int b_coladd = (la_g & 1) << 3;

    for (int c = 0; c < NCH; c++) {
        const int stage = c % GSTAGES;
        cp_wait_group<GSTAGES - 2>();
        __syncthreads();

        const int nc = c + GSTAGES - 1;
        if (nc < NCH) load_chunk(nc, nc % GSTAGES);
        cp_commit();

        const uint32_t base = sb + stage * STAGE_BYTES;
        const uint32_t Bbase = base + 2 * TILE_BYTES;

#pragma unroll
        for (int k16 = 0; k16 < 32; k16 += 16) {
            // B fragments: loaded once, reused for both A segments
            uint32_t bf[4][4];
#pragma unroll
            for (int nb = 0; nb < 4; nb++) {
                const int row = wn * 64 + nb * 16 + b_rowadd;
                const int col = k16 + b_coladd;
                ldmatrix_x4(bf[nb], Bbase + (uint32_t)(row * ROWPAD + col) * 2);
            }
#pragma unroll
            for (int seg = 0; seg < 2; seg++) {
                const uint32_t Abase = base + seg * TILE_BYTES;
                uint32_t af[2][4];
#pragma unroll
                for (int mi = 0; mi < 2; mi++) {
                    const int row = wm * 32 + mi * 16 + a_rowadd;
                    const int col = k16 + a_coladd;
                    ldmatrix_x4(af[mi], Abase + (uint32_t)(row * ROWPAD + col) * 2);
                }
#pragma unroll
                for (int nb = 0; nb < 4; nb++)
#pragma unroll
                    for (int mi = 0; mi < 2; mi++) {
                        mma_f16(acc[mi][nb * 2 + 0], af[mi], bf[nb][0], bf[nb][1]);
                        mma_f16(acc[mi][nb * 2 + 1], af[mi], bf[nb][2], bf[nb][3]);
                    }
            }
        }
    }

    // epilogue
    const int tq = lane >> 2;
    const int tr = lane & 3;
#pragma unroll
    for (int mi = 0; mi < 2; mi++) {
        const int row = m0 + wm * 32 + mi * 16 + tq;
#pragma unroll
        for (int ni = 0; ni < 8; ni++) {
            const int col = n0 + wn * 64 + ni * 8 + tr * 2;
            const float b0 = bias[col], b1 = bias[col + 1];
            float2 v0, v1;
            v0.x = acc[mi][ni][0] + b0; v0.y = acc[mi][ni][1] + b1;
            v1.x = acc[mi][ni][2] + b0; v1.y = acc[mi][ni][3] + b1;
            *(float2*)&C[(size_t)row * Nfull + col] = v0;
            *(float2*)&C[(size_t)(row + 8) * Nfull + col] = v1;
        }
    }
}

// ---------------------------------------------------------------------------
// fp32 -> fp16 hi/lo split (elementwise, float4 vectorized)
// ---------------------------------------------------------------------------
__global__ void cvt_hilo(const float* __restrict__ x, __half* __restrict__ hi,
                         __half* __restrict__ lo, int n4)
{
    int i = blockIdx.x * blockDim.x + threadIdx.x;
    if (i >= n4) return;
    float4 v = ((const float4*)x)[i];
    __half h0 = __float2half_rn(v.x);
    __half h1 = __float2half_rn(v.y);
    __half h2 = __float2half_rn(v.z);
    __half h3 = __float2half_rn(v.w);
    __half l0 = __float2half_rn(v.x - __half2float(h0));
    __half l1 = __float2half_rn(v.y - __half2float(h1));
    __half l2 = __float2half_rn(v.z - __half2float(h2));
    __half l3 = __float2half_rn(v.w - __half2float(h3));
    __half2* hp = (__half2*)hi;
    __half2* lp = (__half2*)lo;
    hp[2 * i + 0] = __half2(h0, h1);
    hp[2 * i + 1] = __half2(h2, h3);
    lp[2 * i + 0] = __half2(l0, l1);
    lp[2 * i + 1] = __half2(l2, l3);
}

// ---------------------------------------------------------------------------
// Weight transpose + fp16 convert:  W[z][Kd][Nd] fp32 -> WT [z][Nd][Kd] fp16
// ---------------------------------------------------------------------------
__global__ void wt_cvt(const float* __restrict__ W, __half* __restrict__ WT,
                       int Kd, int Nd)
{
    __shared__ float t[32][33];
    const size_t moff = (size_t)blockIdx.z * Kd * Nd;
    const float* Wm = W + moff;
    __half* Hh = WT + moff;

    int nx = blockIdx.x * 32 + threadIdx.x;
    int k0 = blockIdx.y * 32;
#pragma unroll
    for (int j = 0; j < 4; j++) {
        int kk = k0 + threadIdx.y + j * 8;
        t[threadIdx.y + j * 8][threadIdx.x] = Wm[(size_t)kk * Nd + nx];
    }
    __syncthreads();
    int kx = k0 + threadIdx.x;
#pragma unroll
    for (int j = 0; j < 4; j++) {
        int nn = blockIdx.x * 32 + threadIdx.y + j * 8;
        Hh[(size_t)nn * Kd + kx] = __float2half_rn(t[threadIdx.x][threadIdx.y + j * 8]);
    }
}

// ---------------------------------------------------------------------------
// Split-K pooled-selection GEMM (fp32, atomics)
// ---------------------------------------------------------------------------
__global__ __launch_bounds__(256, 2)
void gemm_sel_atomic(const float* __restrict__ Wts, const float* __restrict__ Flat,
                     float* __restrict__ Csel)
{
    __shared__ float As[16][128];
    __shared__ float Bs[16][128];

    const int tid = threadIdx.x;
    const int bx = blockIdx.x;
    const int by = blockIdx.y;
    const int b  = blockIdx.z / SPLITK;
    const int sl = blockIdx.z % SPLITK;

    const float* A = Wts  + (size_t)b * MTOK_B * KSEL;
    const float* B = Flat + (size_t)b * MTOK_B * E_DIM;
    float*       C = Csel + (size_t)b * KSEL * E_DIM;

    const int lr = (tid & 31) << 2;
    const int lk = tid >> 5;
    const int tx = tid & 15;
    const int ty = tid >> 4;

    const int kbeg = sl * (MTOK_B / SPLITK);
    const int kend = kbeg + (MTOK_B / SPLITK);

    float acc[8][8];
#pragma unroll
    for (int i = 0; i < 8; i++)
#pragma unroll
        for (int j = 0; j < 8; j++) acc[i][j] = 0.f;

    for (int k0 = kbeg; k0 < kend; k0 += 16) {
        *(float4*)&As[lk][lr]     = *(const float4*)&A[(size_t)(k0 + lk) * KSEL + by * 128 + lr];
        *(float4*)&As[lk + 8][lr] = *(const float4*)&A[(size_t)(k0 + lk + 8) * KSEL + by * 128 + lr];
        *(float4*)&Bs[lk][lr]     = *(const float4*)&B[(size_t)(k0 + lk) * E_DIM + bx * 128 + lr];
        *(float4*)&Bs[lk + 8][lr] = *(const float4*)&B[(size_t)(k0 + lk + 8) * E_DIM + bx * 128 + lr];
        __syncthreads();

#pragma unroll
        for (int kk = 0; kk < 16; kk++) {
            float ar[8], br[8];
            *(float4*)&ar[0] = *(const float4*)&As[kk][ty * 8];
            *(float4*)&ar[4] = *(const float4*)&As[kk][ty * 8 + 4];
            *(float4*)&br[0] = *(const float4*)&Bs[kk][tx * 8];
            *(float4*)&br[4] = *(const float4*)&Bs[kk][tx * 8 + 4];
#pragma unroll
            for (int i = 0; i < 8; i++)
#pragma unroll
                for (int j = 0; j < 8; j++)
                    acc[i][j] += ar[i] * br[j];
        }
        __syncthreads();
    }

#pragma unroll
    for (int i = 0; i < 8; i++) {
        float* cp = C + (size_t)(by * 128 + ty * 8 + i) * E_DIM + bx * 128 + tx * 8;
#pragma unroll
        for (int j = 0; j < 8; j++)
            atomicAdd(&cp[j], acc[i][j]);
    }
}

// ---------------------------------------------------------------------------
// Fused relative-bias multihead attention
// ---------------------------------------------------------------------------
template <int S>
__global__ __launch_bounds__(256)
void attn_kernel(const float* __restrict__ Q, const float* __restrict__ K,
                 const float* __restrict__ V, float* __restrict__ Ctx,
                 const float* __restrict__ rb,
                 int div, int mulq, int mulr, int stepTok)
{
    const int h = blockIdx.x;
    const int g = blockIdx.y;
    const int base_m = (g / div) * mulq + (g % div) * mulr;
    const size_t baseE = (size_t)base_m * E_DIM + h * D_DIM;
    const size_t stepE = (size_t)stepTok * E_DIM;

    extern __shared__ float sm[];
    float2* Kt2 = (float2*)sm;
    float2* Vs2 = Kt2 + 32 * (S + 1);
    float*  rbh = (float*)(Vs2 + S * 32);

    const int tid = threadIdx.x;

    for (int idx = tid; idx < S * 32; idx += 256) {
        int t = idx >> 5, d2 = idx & 31;
        size_t off = baseE + (size_t)t * stepE;
        Kt2[d2 * (S + 1) + t] = *(const float2*)&K[off + 2 * d2];
        Vs2[idx]              = *(const float2*)&V[off + 2 * d2];
    }
    for (int i = tid; i < 2 * S - 1; i += 256)
        rbh[i] = rb[(size_t)(MAXLEN - S + i) * H_DIM + h];
    __syncthreads();

    const int lane = tid & 31;
    const int warp = tid >> 5;
    const int NT = S / 32;

    for (int q = warp; q < S; q += 8) {
        size_t qoff = baseE + (size_t)q * stepE;
        float2 ql = *(const float2*)&Q[qoff + 2 * lane];

        float s[NT];
#pragma unroll
        for (int tb = 0; tb < NT; tb++) s[tb] = 0.f;

#pragma unroll 4
        for (int d2 = 0; d2 < 32; d2++) {
            float qx = __shfl_sync(0xffffffffu, ql.x, d2);
            float qy = __shfl_sync(0xffffffffu, ql.y, d2);
            const float2* kr = &Kt2[d2 * (S + 1) + lane];
#pragma unroll
            for (int tb = 0; tb < NT; tb++) {
                float2 kv = kr[tb * 32];
                s[tb] += qx * kv.x + qy * kv.y;
            }
        }

#pragma unroll
        for (int tb = 0; tb < NT; tb++) {
            int t = tb * 32 + lane;
            s[tb] = s[tb] * 0.125f + rbh[t - q + (S - 1)];
        }

        float mx = s[0];
#pragma unroll
        for (int tb = 1; tb < NT; tb++) mx = fmaxf(mx, s[tb]);
#pragma unroll
        for (int o = 16; o > 0; o >>= 1)
            mx = fmaxf(mx, __shfl_xor_sync(0xffffffffu, mx, o));
        float sum = 0.f;
#pragma unroll
        for (int tb = 0; tb < NT; tb++) { s[tb] = __expf(s[tb] - mx); sum += s[tb]; }
#pragma unroll
        for (int o = 16; o > 0; o >>= 1)
            sum += __shfl_xor_sync(0xffffffffu, sum, o);
        float inv = 1.f / sum;
#pragma unroll
        for (int tb = 0; tb < NT; tb++) s[tb] *= inv;

        float cx = 0.f, cy = 0.f;
#pragma unroll
        for (int tb = 0; tb < NT; tb++) {
            float wv = s[tb];
#pragma unroll 8
            for (int j = 0; j < 32; j++) {
                float wj = __shfl_sync(0xffffffffu, wv, j);
                float2 vv = Vs2[(tb * 32 + j) * 32 + lane];
                cx += wj * vv.x;
                cy += wj * vv.y;
            }
        }
        float2 cw; cw.x = cx; cw.y = cy;
        *(float2*)&Ctx[qoff + 2 * lane] = cw;
    }
}

// ---------------------------------------------------------------------------
// Selection softmax over token axis per (b, k), in place
// ---------------------------------------------------------------------------
__global__ __launch_bounds__(256)
void sel_softmax(float* __restrict__ sc)
{
    const int b = blockIdx.x;
    const int k0 = blockIdx.y * 32;
    const int lane = threadIdx.x & 31;
    const int row = threadIdx.x >> 5;

    float* base = sc + (size_t)b * MTOK_B * KSEL + k0 + lane;

    __shared__ float redA[8][32];
    __shared__ float redB[8][32];

    float mx = -1e30f;
    for (int m = row; m < MTOK_B; m += 8)
        mx = fmaxf(mx, base[(size_t)m * KSEL]);
    redA[row][lane] = mx;
    __syncthreads();
    if (row == 0) {
        float v = redA[0][lane];
#pragma unroll
        for (int r = 1; r < 8; r++) v = fmaxf(v, redA[r][lane]);
        redA[0][lane] = v;
    }
    __syncthreads();
    mx = redA[0][lane];

    float sum = 0.f;
    for (int m = row; m < MTOK_B; m += 8)
        sum += __expf(base[(size_t)m * KSEL] - mx);
    redB[row][lane] = sum;
    __syncthreads();
    if (row == 0) {
        float v = 0.f;
#pragma unroll
        for (int r = 0; r < 8; r++) v += redB[r][lane];
        redB[0][lane] = v;
    }
    __syncthreads();
    float inv = 1.f / redB[0][lane];

    for (int m = row; m < MTOK_B; m += 8) {
        float* p = &base[(size_t)m * KSEL];
        *p = __expf(*p - mx) * inv;
    }
}

// ---------------------------------------------------------------------------
// Multi-scale pooling
// ---------------------------------------------------------------------------
__global__ void pool_kernel(const float* __restrict__ sel, float* __restrict__ out)
{
    int idx = blockIdx.x * blockDim.x + threadIdx.x;
    int total = B_DIM * OUT_ROWS * E_DIM;
    if (idx >= total) return;
    int e = idx % E_DIM;
    int r = (idx / E_DIM) % OUT_ROWS;
    int b = idx / (OUT_ROWS * E_DIM);
    const float* sb = sel + (size_t)b * KSEL * E_DIM;
    float v;
    if (r < 256) {
        v = sb[(size_t)r * E_DIM + e];
    } else if (r < 384) {
        int i = (r - 256) * 2;
        v = 0.5f * (sb[(size_t)i * E_DIM + e] + sb[(size_t)(i + 1) * E_DIM + e]);
    } else {
        int i = (r - 384) * 4;
        v = 0.25f * (sb[(size_t)i * E_DIM + e] + sb[(size_t)(i + 1) * E_DIM + e] +
                     sb[(size_t)(i + 2) * E_DIM + e] + sb[(size_t)(i + 3) * E_DIM + e]);
    }
    out[idx] = v;
}

// ---------------------------------------------------------------------------
// Orchestration
// ---------------------------------------------------------------------------
extern "C" void kernel_launch(void* const* d_in, const int* in_sizes, int n_in,
                              void* d_out, int out_size)
{
    (void)in_sizes; (void)n_in; (void)out_size;

    const float* x    = (const float*)d_in[0];
    const float* wq   = (const float*)d_in[1];
    const float* bq   = (const float*)d_in[2];
    const float* wk   = (const float*)d_in[3];
    const float* bk   = (const float*)d_in[4];
    const float* wv   = (const float*)d_in[5];
    const float* bv   = (const float*)d_in[6];
    const float* wd   = (const float*)d_in[7];
    const float* bd   = (const float*)d_in[8];
    const float* rb   = (const float*)d_in[9];
    const float* selw = (const float*)d_in[10];
    const float* selb = (const float*)d_in[11];
    float* out = (float*)d_out;

    float *Qb, *Kb, *Vb, *Cb, *Hb, *SCb, *SELb;
    cudaGetSymbolAddress((void**)&Qb,  g_Q);
    cudaGetSymbolAddress((void**)&Kb,  g_Kb);
    cudaGetSymbolAddress((void**)&Vb,  g_Vb);
    cudaGetSymbolAddress((void**)&Cb,  g_Cb);
    cudaGetSymbolAddress((void**)&Hb,  g_Hb);
    cudaGetSymbolAddress((void**)&SCb, g_SC);
    cudaGetSymbolAddress((void**)&SELb, g_SEL);

    __half *Ahp, *Alp, *WqT, *WkT, *WvT, *WdT, *SWT;
    cudaGetSymbolAddress((void**)&Ahp, g_Ah);
    cudaGetSymbolAddress((void**)&Alp, g_Al);
    cudaGetSymbolAddress((void**)&WqT, g_WqT);
    cudaGetSymbolAddress((void**)&WkT, g_WkT);
    cudaGetSymbolAddress((void**)&WvT, g_WvT);
    cudaGetSymbolAddress((void**)&WdT, g_WdT);
    cudaGetSymbolAddress((void**)&SWT, g_SWT);

    const int smemSp = (32 * (256 + 1) * 2 + 256 * 32 * 2 + (2 * 256 - 1)) * (int)sizeof(float);
    const int smemTe = (32 * (32 + 1) * 2 + 32 * 32 * 2 + (2 * 32 - 1)) * (int)sizeof(float);
    cudaFuncSetAttribute((const void*)attn_kernel<256>,
                         cudaFuncAttributeMaxDynamicSharedMemorySize, smemSp);
    cudaFuncSetAttribute((const void*)gemm_f16x2,
                         cudaFuncAttributeMaxDynamicSharedMemorySize, GEMM_SMEM);

    const dim3 blk(256);
    const dim3 tblk(32, 8);

    // weight transpose + fp16 convert (once per call)
    wt_cvt<<<dim3(E_DIM / 32, E_DIM / 32, 4), tblk>>>(wq, WqT, E_DIM, E_DIM);
    wt_cvt<<<dim3(E_DIM / 32, E_DIM / 32, 4), tblk>>>(wk, WkT, E_DIM, E_DIM);
    wt_cvt<<<dim3(E_DIM / 32, E_DIM / 32, 4), tblk>>>(wv, WvT, E_DIM, E_DIM);
    wt_cvt<<<dim3(E_DIM / 32, E_DIM / 32, 4), tblk>>>(wd, WdT, E_DIM, E_DIM);
    wt_cvt<<<dim3(KSEL / 32, E_DIM / 32, 1), tblk>>>(selw, SWT, E_DIM, KSEL);

    const int n4 = MTOK * E_DIM / 4;
    const dim3 gcvt((n4 + 255) / 256);
    const dim3 gProj(E_DIM / 128, MTOK / 128);    // 8 x 128 CTAs
    const size_t MM = (size_t)E_DIM * E_DIM;

    for (int a = 0; a < 4; a++) {
        const float* src = (a == 0) ? x : Hb;
        cvt_hilo<<<gcvt, blk>>>(src, Ahp, Alp, n4);
        gemm_f16x2<<<gProj, blk, GEMM_SMEM>>>(Ahp, Alp, WqT + a * MM, bq + a * E_DIM, Qb, E_DIM, E_DIM);
        gemm_f16x2<<<gProj, blk, GEMM_SMEM>>>(Ahp, Alp, WkT + a * MM, bk + a * E_DIM, Kb, E_DIM, E_DIM);
        gemm_f16x2<<<gProj, blk, GEMM_SMEM>>>(Ahp, Alp, WvT + a * MM, bv + a * E_DIM, Vb, E_DIM, E_DIM);

        const float* rba = rb + (size_t)a * RB_ONE;
        if ((a & 1) == 0) {
            attn_kernel<256><<<dim3(H_DIM, B_DIM * T_DIM), blk, smemSp>>>(
                Qb, Kb, Vb, Cb, rba, B_DIM * T_DIM, 0, N_DIM, 1);
        } else {
            attn_kernel<32><<<dim3(H_DIM, B_DIM * N_DIM), blk, smemTe>>>(
                Qb, Kb, Vb, Cb, rba, N_DIM, T_DIM * N_DIM, 1, N_DIM);
        }

        cvt_hilo<<<gcvt, blk>>>(Cb, Ahp, Alp, n4);
        gemm_f16x2<<<gProj, blk, GEMM_SMEM>>>(Ahp, Alp, WdT + a * MM, bd + a * E_DIM, Hb, E_DIM, E_DIM);
    }

    // selection scores: [MTOK, KSEL]
    cvt_hilo<<<gcvt, blk>>>(Hb, Ahp, Alp, n4);
    gemm_f16x2<<<dim3(KSEL / 128, MTOK / 128), blk, GEMM_SMEM>>>(Ahp, Alp, SWT, selb, SCb, KSEL, E_DIM);

    // softmax over token axis per (b, k), in place
    sel_softmax<<<dim3(B_DIM, KSEL / 32), blk>>>(SCb);

    // sel[b,k,e] = sum_m wts[b,m,k] * h[b,m,e]  (split-K + atomics)
    cudaMemsetAsync(SELb, 0, (size_t)B_DIM * KSEL * E_DIM * sizeof(float));
    gemm_sel_atomic<<<dim3(E_DIM / 128, KSEL / 128, B_DIM * SPLITK), blk>>>(SCb, Hb, SELb);

    // multi-scale pooling -> output [B, 448, E]
    int total = B_DIM * OUT_ROWS * E_DIM;
    pool_kernel<<<(total + 255) / 256, 256>>>(SELb, out);
}